// round 7
// baseline (speedup 1.0000x reference)
#include <cuda_runtime.h>
#include <math.h>

#define NSEG    2047
#define NPIX    16384
#define NTILE   512          // 16 x-tiles (8px) * 32 y-tiles (4px)
#define NCAP    512          // direct smem candidate capacity
#define GAMMA_F 200.0f
#define STEPF   (2.0f / 127.0f)
// tile = 8x4 px, center (+3.5,+1.5): 2*half-diag = 2*sqrt(3.5^2+1.5^2) px
#define THR_ADD (7.615773f * STEPF + 1e-3f)
#define FINF    __int_as_float(0x7F800000)

__device__ __forceinline__ float satmul(float a, float b) {
    float r; asm("mul.rn.sat.f32 %0,%1,%2;" : "=f"(r) : "f"(a), "f"(b)); return r;
}

// Cross-CTA state, reset by the last loss-CTA every run (graph-replay safe).
__device__ float    g_pix[2][NPIX];
__device__ int      g_tile_cnt[NTILE];
__device__ float    g_loss = 0.0f;
__device__ unsigned g_done = 0;

// ---------------------------------------------------------------------------
// grid 1024 x 128: bid = w*512 + tile (8x4 px).
// Phase 1: 16 segs/thread, in-register conversion, center eval, block-min U,
//          exact triangle-inequality cull. Survivors are CONVERTED AND WRITTEN
//          DIRECTLY into s_seg/s_inv (no index list, no staging pass).
// Phase 2: thread = (pixel-pair p=tid&15 [same row, cols c & c+4], slice
//          h=tid>>4 of 8); streams s_seg sequentially, 2 chains/pixel.
// Overflow (>512 candidates; not hit on this data): cold path from global.
// Pairing/loss/reset identical to R6.
// ---------------------------------------------------------------------------
__global__ void __launch_bounds__(128) fused_kernel(const float* __restrict__ pred,
                                                    const float* __restrict__ gt,
                                                    float* __restrict__ out) {
    const int tid  = threadIdx.x;
    const int bid  = blockIdx.x;
    const int w    = bid >> 9;
    const int tile = bid & (NTILE - 1);
    const int tx = tile & 15, ty = tile >> 4;

    const float* __restrict__ c = w ? gt : pred;

    const float cx = fmaf((float)(tx * 8) + 3.5f, STEPF, -1.0f);
    const float cy = fmaf((float)(ty * 4) + 1.5f, STEPF, -1.0f);

    // pixel pair: row prow, cols pcol and pcol+4 ; slice h8 of 8
    const int pairp = tid & 15;
    const int h8    = tid >> 4;
    const int prow  = pairp >> 2;
    const int pcol  = pairp & 3;
    const float gy  = fmaf((float)(ty * 4 + prow), STEPF, -1.0f);
    const float gx0 = fmaf((float)(tx * 8 + pcol), STEPF, -1.0f);
    const float gx1 = fmaf((float)(tx * 8 + pcol + 4), STEPF, -1.0f);

    __shared__ float4 s_seg[NCAP];            // 8 KB
    __shared__ float  s_inv[NCAP];            // 2 KB
    __shared__ unsigned short s_ovf[NSEG - NCAP + 1];   // ~3 KB, cold
    __shared__ float  s_mA[16][8], s_mB[16][8];
    __shared__ float  s_red[4];
    __shared__ int    s_cnt;
    __shared__ int    s_flag;

    if (tid == 0) s_cnt = 0;

    // ---------------- Phase 1: center eval + cull ----------------
    float d2c[16];
    float lmin = FINF;
#pragma unroll
    for (int k = 0; k < 16; ++k) {
        const int s = tid + (k << 7);
        float d2 = FINF;
        if (s < NSEG) {
            const float pen = __ldg(&c[s * 3 + 2]);
            const bool masked = w ? (pen != 0.0f) : (pen > 0.5f);
            float pjx = fmaf(__ldg(&c[s * 3 + 3]), 2.0f, -1.0f);
            float pjy = fmaf(__ldg(&c[s * 3 + 4]), 2.0f, -1.0f);
            float vx  = fmaf(__ldg(&c[s * 3 + 0]), 2.0f, -1.0f) - pjx;
            float vy  = fmaf(__ldg(&c[s * 3 + 1]), 2.0f, -1.0f) - pjy;
            const float vn = vx * vx + vy * vy;
            float inv = (vn == 0.0f) ? 0.0f : (1.0f / vn);
            if (masked) { pjx = 1e9f; pjy = 1e9f; vx = 0.0f; vy = 0.0f; inv = 0.0f; }
            const float ux = cx - pjx, uy = cy - pjy;
            const float uv = fmaf(ux, vx, uy * vy);
            const float t  = satmul(uv, inv);
            const float dx = fmaf(-t, vx, ux);
            const float dy = fmaf(-t, vy, uy);
            d2 = fmaf(dy, dy, dx * dx);
        }
        d2c[k] = d2;
        lmin = fminf(lmin, d2);
    }
#pragma unroll
    for (int o = 16; o > 0; o >>= 1)
        lmin = fminf(lmin, __shfl_xor_sync(0xFFFFFFFFu, lmin, o));
    if ((tid & 31) == 0) s_red[tid >> 5] = lmin;
    __syncthreads();
    const float U   = fminf(fminf(s_red[0], s_red[1]), fminf(s_red[2], s_red[3]));
    const float thd = sqrtf(U) + THR_ADD;
    const float thr = thd * thd;

    // survivors: convert + write directly into candidate SoA
#pragma unroll
    for (int k = 0; k < 16; ++k) {
        if (d2c[k] < thr) {
            const int s   = tid + (k << 7);
            const int pos = atomicAdd(&s_cnt, 1);
            if (pos < NCAP) {
                const float pen = __ldg(&c[s * 3 + 2]);
                const bool masked = w ? (pen != 0.0f) : (pen > 0.5f);
                float pjx = fmaf(__ldg(&c[s * 3 + 3]), 2.0f, -1.0f);
                float pjy = fmaf(__ldg(&c[s * 3 + 4]), 2.0f, -1.0f);
                float vx  = fmaf(__ldg(&c[s * 3 + 0]), 2.0f, -1.0f) - pjx;
                float vy  = fmaf(__ldg(&c[s * 3 + 1]), 2.0f, -1.0f) - pjy;
                const float vn = vx * vx + vy * vy;
                float inv = (vn == 0.0f) ? 0.0f : (1.0f / vn);
                if (masked) { pjx = 1e9f; pjy = 1e9f; vx = 0.0f; vy = 0.0f; inv = 0.0f; }
                s_seg[pos] = make_float4(pjx, pjy, vx, vy);
                s_inv[pos] = inv;
            } else {
                s_ovf[pos - NCAP] = (unsigned short)s;
            }
        }
    }
    __syncthreads();

    // ---------------- Phase 2: stream candidates, 2 px/thread ----------------
    const int len = s_cnt;
    const int n1  = (len < NCAP) ? len : NCAP;
    float mA0 = FINF, mA1 = FINF, mB0 = FINF, mB1 = FINF;

#define EVAL2(J, MA, MB)                                            \
    {                                                               \
        const float4 q = s_seg[J]; const float inv = s_inv[J];      \
        const float uy  = gy - q.y;                                 \
        const float cyv = uy * q.w;                                 \
        const float ux0 = gx0 - q.x;                                \
        const float uv0 = fmaf(ux0, q.z, cyv);                      \
        const float t0  = satmul(uv0, inv);                         \
        const float dxa = fmaf(-t0, q.z, ux0);                      \
        const float dya = fmaf(-t0, q.w, uy);                       \
        MA = fminf(MA, fmaf(dya, dya, dxa * dxa));                  \
        const float ux1 = gx1 - q.x;                                \
        const float uv1 = fmaf(ux1, q.z, cyv);                      \
        const float t1  = satmul(uv1, inv);                         \
        const float dxb = fmaf(-t1, q.z, ux1);                      \
        const float dyb = fmaf(-t1, q.w, uy);                       \
        MB = fminf(MB, fmaf(dyb, dyb, dxb * dxb));                  \
    }

    int j = h8;
    for (; j + 8 < n1; j += 16) {
        EVAL2(j,     mA0, mB0)
        EVAL2(j + 8, mA1, mB1)
    }
    for (; j < n1; j += 8) {
        EVAL2(j, mA0, mB0)
    }

    // cold overflow path (len > NCAP): every thread walks the tail
    if (len > NCAP) {
        const int novf = len - NCAP;
        for (int o2 = 0; o2 < novf; ++o2) {
            const int s = s_ovf[o2];
            const float pen = __ldg(&c[s * 3 + 2]);
            const bool masked = w ? (pen != 0.0f) : (pen > 0.5f);
            float pjx = fmaf(__ldg(&c[s * 3 + 3]), 2.0f, -1.0f);
            float pjy = fmaf(__ldg(&c[s * 3 + 4]), 2.0f, -1.0f);
            float vx  = fmaf(__ldg(&c[s * 3 + 0]), 2.0f, -1.0f) - pjx;
            float vy  = fmaf(__ldg(&c[s * 3 + 1]), 2.0f, -1.0f) - pjy;
            const float vn = vx * vx + vy * vy;
            float inv = (vn == 0.0f) ? 0.0f : (1.0f / vn);
            if (masked) { pjx = 1e9f; pjy = 1e9f; vx = 0.0f; vy = 0.0f; inv = 0.0f; }
            const float uy  = gy - pjy;
            const float cyv = uy * vy;
            float ux = gx0 - pjx;
            float uv = fmaf(ux, vx, cyv);
            float t  = satmul(uv, inv);
            float dx = fmaf(-t, vx, ux);
            float dy = fmaf(-t, vy, uy);
            mA0 = fminf(mA0, fmaf(dy, dy, dx * dx));
            ux = gx1 - pjx;
            uv = fmaf(ux, vx, cyv);
            t  = satmul(uv, inv);
            dx = fmaf(-t, vx, ux);
            dy = fmaf(-t, vy, uy);
            mB0 = fminf(mB0, fmaf(dy, dy, dx * dx));
        }
    }

    s_mA[pairp][h8] = fminf(mA0, mA1);
    s_mB[pairp][h8] = fminf(mB0, mB1);
    __syncthreads();

    // ---------------- Merge slices, publish mins, pair up ----------------
    const int pixbase = (ty * 4) * 128 + tx * 8;
    float qown = 0.0f;
    if (tid < 32) {
        const int row = tid >> 3, col = tid & 7;
        const int pp  = (row << 2) | (col & 3);
        const float* arr = (col < 4) ? s_mA[pp] : s_mB[pp];
        qown = fminf(fminf(fminf(arr[0], arr[1]), fminf(arr[2], arr[3])),
                     fminf(fminf(arr[4], arr[5]), fminf(arr[6], arr[7])));
        g_pix[w][pixbase + row * 128 + col] = qown;
    }
    __threadfence();
    if (tid == 0) {
        const int old = atomicAdd(&g_tile_cnt[tile], 1);
        s_flag = (old == 1);
    }
    __syncthreads();

    // ---------------- Second arriver: tile loss partial ----------------
    if (s_flag) {
        float v = 0.0f;
        if (tid < 32) {
            const int row = tid >> 3, col = tid & 7;
            const float qoth = g_pix[w ^ 1][pixbase + row * 128 + col];
            const float bo = expf(-GAMMA_F * qown);
            const float bt = expf(-GAMMA_F * qoth);
            const float d  = bo - bt;
            v = d * d;
#pragma unroll
            for (int o = 16; o > 0; o >>= 1)
                v += __shfl_xor_sync(0xFFFFFFFFu, v, o);
        }
        if (tid == 0) {
            atomicAdd(&g_loss, v);
            __threadfence();
            const unsigned old2 = atomicAdd(&g_done, 1u);
            s_flag = (old2 == NTILE - 1) ? 2 : 0;
        }
        __syncthreads();

        // ---------------- Last loss-CTA: finalize + reset ----------------
        if (s_flag == 2) {
            for (int i = tid; i < NTILE; i += 128) g_tile_cnt[i] = 0;
            if (tid == 0) {
                const float total = *((volatile float*)&g_loss);
                out[0] = total * (1.0f / (float)NPIX);
                g_loss = 0.0f;
                g_done = 0u;
            }
        }
    }
}

// ---------------------------------------------------------------------------
extern "C" void kernel_launch(void* const* d_in, const int* in_sizes, int n_in,
                              void* d_out, int out_size) {
    const float* pred = (const float*)d_in[0];
    const float* gt   = (const float*)d_in[1];
    float* out = (float*)d_out;

    fused_kernel<<<1024, 128>>>(pred, gt, out);
}